// round 5
// baseline (speedup 1.0000x reference)
#include <cuda_runtime.h>
#include <stdint.h>

#define HW 16384   // 128*128

// ---- device scratch ----
__device__ float g_pool[4 * 8 * 128 * 15];   // [br][b][c][pos]
__device__ float g_Wfold[8 * 96 * 16];       // Whh @ W_center per group
__device__ float g_Gi[8 * 8 * 96 * 15];      // [b][g][o][pos] (includes bih)

// ---- helpers ----
__device__ __forceinline__ float tanhfast(float x) {
    float y; asm("tanh.approx.f32 %0, %1;" : "=f"(y) : "f"(x)); return y;
}
__device__ __forceinline__ float sigfast(float x) {
    return fmaf(0.5f, tanhfast(0.5f * x), 0.5f);
}
__device__ __forceinline__ uint32_t cvt_tf32(float f) {
    uint32_t r; asm("cvt.rna.tf32.f32 %0, %1;" : "=r"(r) : "f"(f)); return r;
}
__device__ __forceinline__ uint64_t pack2(float a, float b) {
    uint64_t r; asm("mov.b64 %0, {%1,%2};" : "=l"(r) : "f"(a), "f"(b)); return r;
}
__device__ __forceinline__ void unpack2(uint64_t v, float& a, float& b) {
    asm("mov.b64 {%0,%1}, %2;" : "=f"(a), "=f"(b) : "l"(v));
}
__device__ __forceinline__ void add2(uint64_t& d, uint64_t v) {
    asm("add.rn.f32x2 %0, %0, %1;" : "+l"(d) : "l"(v));
}
__device__ __forceinline__ void mma_acc(float d[4], const uint32_t a[4],
                                        uint32_t b0, uint32_t b1) {
    asm("mma.sync.aligned.m16n8k8.row.col.f32.tf32.tf32.f32 "
        "{%0,%1,%2,%3},{%4,%5,%6,%7},{%8,%9},{%0,%1,%2,%3};"
        : "+f"(d[0]), "+f"(d[1]), "+f"(d[2]), "+f"(d[3])
        : "r"(a[0]), "r"(a[1]), "r"(a[2]), "r"(a[3]), "r"(b0), "r"(b1));
}
__device__ __forceinline__ void mma_init(float d[4], const uint32_t a[4],
                                         uint32_t b0, uint32_t b1,
                                         float c0, float c1) {
    asm("mma.sync.aligned.m16n8k8.row.col.f32.tf32.tf32.f32 "
        "{%0,%1,%2,%3},{%4,%5,%6,%7},{%8,%9},{%10,%11,%10,%11};"
        : "=f"(d[0]), "=f"(d[1]), "=f"(d[2]), "=f"(d[3])
        : "r"(a[0]), "r"(a[1]), "r"(a[2]), "r"(a[3]), "r"(b0), "r"(b1),
          "f"(c0), "f"(c1));
}
__device__ __forceinline__ uint32_t coef_tf32(int pos, int j0, float fw) {
    float c = (pos == j0) ? (1.0f - fw) : ((pos == j0 + 1) ? fw : 0.0f);
    return cvt_tf32(c);
}

// ============================================================================
// K1: adaptive pools. grid 256 = (b, c4); warp <-> channel, lane owns 4 cols.
// float4 loads + f32x2 accumulation; bin indices compile-time via full unroll.
// ============================================================================
__global__ __launch_bounds__(128) void pool_kernel(const float* __restrict__ x) {
    const int blk = blockIdx.x;           // 0..255
    const int b = blk >> 5, c4 = blk & 31;
    const int warp = threadIdx.x >> 5, lane = threadIdx.x & 31;
    const int c = c4 * 4 + warp;
    const float4* tile = (const float4*)(x + ((size_t)(b * 128 + c)) * HW) + lane;

    uint64_t a0[2];
    uint64_t a1[11][2], a2[3][2], a3[5][2];
    a0[0] = a0[1] = 0ull;
    #pragma unroll
    for (int i = 0; i < 11; i++) { a1[i][0] = a1[i][1] = 0ull; }
    #pragma unroll
    for (int i = 0; i < 3; i++) { a2[i][0] = a2[i][1] = 0ull; }
    #pragma unroll
    for (int i = 0; i < 5; i++) { a3[i][0] = a3[i][1] = 0ull; }

    #pragma unroll
    for (int h = 0; h < 128; h++) {
        float4 v = tile[h * 32];
        uint64_t vlo = pack2(v.x, v.y), vhi = pack2(v.z, v.w);
        add2(a0[0], vlo); add2(a0[1], vhi);
        {
            const int p = (h * 11) >> 7;
            add2(a1[p][0], vlo); add2(a1[p][1], vhi);
            if (p + 1 < 11 && h == ((p + 1) * 128) / 11 && (((p + 1) * 128) % 11) != 0) {
                add2(a1[p + 1][0], vlo); add2(a1[p + 1][1], vhi);
            }
        }
        {
            const int p = (h * 3) >> 7;
            add2(a2[p][0], vlo); add2(a2[p][1], vhi);
            if (p + 1 < 3 && h == ((p + 1) * 128) / 3 && (((p + 1) * 128) % 3) != 0) {
                add2(a2[p + 1][0], vlo); add2(a2[p + 1][1], vhi);
            }
        }
        {
            const int p = (h * 5) >> 7;
            add2(a3[p][0], vlo); add2(a3[p][1], vhi);
            if (p + 1 < 5 && h == ((p + 1) * 128) / 5 && (((p + 1) * 128) % 5) != 0) {
                add2(a3[p + 1][0], vlo); add2(a3[p + 1][1], vhi);
            }
        }
    }

    __shared__ float4 cs[4][20][32];      // [ch][bin][lane] 4-col sums
    {
        float4 v;
        unpack2(a0[0], v.x, v.y); unpack2(a0[1], v.z, v.w);
        cs[warp][0][lane] = v;
        #pragma unroll
        for (int i = 0; i < 11; i++) {
            unpack2(a1[i][0], v.x, v.y); unpack2(a1[i][1], v.z, v.w);
            cs[warp][1 + i][lane] = v;
        }
        #pragma unroll
        for (int i = 0; i < 3; i++) {
            unpack2(a2[i][0], v.x, v.y); unpack2(a2[i][1], v.z, v.w);
            cs[warp][12 + i][lane] = v;
        }
        #pragma unroll
        for (int i = 0; i < 5; i++) {
            unpack2(a3[i][0], v.x, v.y); unpack2(a3[i][1], v.z, v.w);
            cs[warp][15 + i][lane] = v;
        }
    }
    __syncwarp();

    const float* csf = (const float*)&cs[warp][0][0];   // [20][128]
    for (int oi = 0; oi < 52; oi++) {
        int br, pos, row, ws, we, hs, he;
        if (oi < 11) {
            br = 0; pos = oi; row = 0;
            hs = 0; he = 128;
            ws = (pos * 128) / 11; we = ((pos + 1) * 128 + 10) / 11;
        } else if (oi < 22) {
            br = 1; pos = oi - 11; row = 1 + pos;
            ws = 0; we = 128;
            hs = (pos * 128) / 11; he = ((pos + 1) * 128 + 10) / 11;
        } else if (oi < 37) {
            br = 2; pos = oi - 22;
            int i = pos / 5, jj = pos % 5;
            row = 12 + i;
            hs = (i * 128) / 3;  he = ((i + 1) * 128 + 2) / 3;
            ws = (jj * 128) / 5; we = ((jj + 1) * 128 + 4) / 5;
        } else {
            br = 3; pos = oi - 37;
            int i = pos / 3, jj = pos % 3;
            row = 15 + i;
            hs = (i * 128) / 5;  he = ((i + 1) * 128 + 4) / 5;
            ws = (jj * 128) / 3; we = ((jj + 1) * 128 + 2) / 3;
        }
        float s = 0.0f;
        for (int w = ws + lane; w < we; w += 32) s += csf[row * 128 + w];
        #pragma unroll
        for (int off = 16; off; off >>= 1) s += __shfl_down_sync(0xffffffffu, s, off);
        if (lane == 0)
            g_pool[((br * 8 + b) * 128 + c) * 15 + pos] =
                s / (float)((he - hs) * (we - ws));
    }
}

// ============================================================================
// K2: fused branch-linear + merge + Wih -> Gi (blocks 0..127, 2 per (b,g)),
//     plus Wfold = Whh @ W_center (blocks 128..135).
// ============================================================================
__global__ __launch_bounds__(256) void gi_fold_kernel(
    const float* __restrict__ W0, const float* __restrict__ b0,
    const float* __restrict__ W1, const float* __restrict__ b1,
    const float* __restrict__ W2, const float* __restrict__ b2,
    const float* __restrict__ W3, const float* __restrict__ b3,
    const float* __restrict__ Wm, const float* __restrict__ Wih,
    const float* __restrict__ bih,
    const float* __restrict__ Whh, const float* __restrict__ Wcen)
{
    const int blk = blockIdx.x;
    const int t = threadIdx.x;

    if (blk >= 128) {              // fold part
        int g = blk - 128;
        if (t < 96) {
            int o = t;
            #pragma unroll 4
            for (int i = 0; i < 16; i++) {
                float s = 0.0f;
                #pragma unroll
                for (int hh = 0; hh < 32; hh++)
                    s = fmaf(Whh[(g * 96 + o) * 32 + hh], Wcen[(g * 32 + hh) * 16 + i], s);
                g_Wfold[(g * 96 + o) * 16 + i] = s;
            }
        }
        return;
    }

    const int b = blk >> 4, g = (blk >> 1) & 7, half = blk & 1;
    const int br = g >> 1;
    const int GS = (br < 2) ? 11 : 15;
    const float* Ws[4] = {W0, W1, W2, W3};
    const float* bs[4] = {b0, b1, b2, b3};
    const float* W = Ws[br];
    const float* bias = bs[br];
    const int c0 = 64 * (g & 1);

    __shared__ float q[64 * 15];
    __shared__ float Bs[32 * 15];

    for (int idx = t; idx < 64 * GS; idx += 256) {
        int cc = idx / GS, m = idx - cc * GS;
        const float* src = g_pool + ((br * 8 + b) * 128 + c0 + cc) * 15;
        float s = bias[m];
        for (int d = 0; d < GS; d++) s = fmaf(W[m * GS + d], src[d], s);
        q[cc * GS + m] = s;
    }
    __syncthreads();

    for (int idx = t; idx < 32 * GS; idx += 256) {
        int f = idx / GS, pos = idx - f * GS;
        int i = 16 * g + (f >> 1), jm = f & 1;
        const float* qb = q + (4 * (f >> 1)) * GS + pos;
        float s = 0.0f;
        #pragma unroll
        for (int k = 0; k < 4; k++)
            s = fmaf(Wm[(i * 2 + jm) * 4 + k], qb[k * GS], s);
        Bs[f * GS + pos] = s;
    }
    __syncthreads();

    const int obase = half * 48;
    for (int idx = t; idx < 48 * GS; idx += 256) {
        int o = obase + idx / GS, pos = idx % GS;
        float s = bih[g * 96 + o];
        #pragma unroll 8
        for (int f = 0; f < 32; f++)
            s = fmaf(Wih[(g * 96 + o) * 32 + f], Bs[f * GS + pos], s);
        g_Gi[((b * 8 + g) * 96 + o) * 15 + pos] = s;
    }
}

// ============================================================================
// K3: main kernel. tf32 mma with w-interp folded into extra K-steps.
// grid (128, 8): g = blockIdx.y; b = blockIdx.x>>4; warp = one image row.
// Per half (j in [16e,16e+16)): tiles r,z (K=16+OW coefs), hn,cg (K=16),
// gin (K=OW coefs only). acc = 10 tiles x 4 = 40 regs live.
// ============================================================================
template<int OH, int OW>
__device__ __forceinline__ void run_group(
    int g, int b, const float* __restrict__ x, const float* __restrict__ bhh,
    float* __restrict__ out, const float2* Wsm, float* xsp, float* gbuf)
{
    constexpr int KB = (OW > 8) ? 2 : (OW > 1 ? 1 : 0);
    const int t = threadIdx.x;
    const int warp = t >> 5, lane = t & 31;
    const int p = lane >> 2, q = lane & 3;
    const int h = ((blockIdx.x & 15) << 3) + warp;
    const float* gib = g_Gi + (size_t)((b * 8 + g) * 96) * 15;

    // ---- build interp structures ----
    if (OW == 1) {
        // per-warp row-interpolated values (row-constant gi)
        float src = (float)(h * (OH - 1)) * (1.0f / 127.0f);
        int ih0 = (int)src; if (ih0 > OH - 2) ih0 = OH - 2;
        float fh = src - (float)ih0;
        for (int j = lane; j < 96; j += 32) {
            float v0 = gib[j * 15 + ih0];
            float v1 = gib[j * 15 + ih0 + 1];
            float v = fmaf(fh, v1 - v0, v0);
            if (j < 64) v += bhh[g * 96 + j];
            gbuf[warp * 96 + j] = v;
        }
    } else if (OH == 1) {
        // shared growp: [kb][G][j][q] float2 {pos 8kb+q, pos 8kb+q+4}
        float2* gp = (float2*)gbuf;
        for (int idx = t; idx < KB * 3 * 32 * 4; idx += 256) {
            int qq = idx & 3, j = (idx >> 2) & 31;
            int Gk = idx >> 7, G = Gk % 3, kb = Gk / 3;
            int jg = (G == 2) ? (64 + j) : (G * 32 + j);
            int pos0 = kb * 8 + qq, pos1 = pos0 + 4;
            float vx = 0.0f, vy = 0.0f;
            if (pos0 < OW) vx = gib[jg * 15 + pos0];
            if (pos1 < OW) vy = gib[jg * 15 + pos1];
            if (G < 2) {
                float bv = bhh[g * 96 + jg];
                if (pos0 < OW) vx += bv;
                if (pos1 < OW) vy += bv;
            }
            gp[idx] = make_float2(__uint_as_float(cvt_tf32(vx)),
                                  __uint_as_float(cvt_tf32(vy)));
        }
    } else {
        // per-warp growp: [G][j][q] float2, h-interpolated
        float2* gp = (float2*)gbuf + warp * 384;
        float src = (float)(h * (OH - 1)) * (1.0f / 127.0f);
        int ih0 = (int)src; if (ih0 > OH - 2) ih0 = OH - 2;
        float fh = src - (float)ih0;
        for (int idx = lane; idx < 3 * 32 * 4; idx += 32) {
            int qq = idx & 3, j = (idx >> 2) & 31, G = idx >> 7;
            int jg = (G == 2) ? (64 + j) : (G * 32 + j);
            float vx = 0.0f, vy = 0.0f;
            if (qq < OW) {
                float v0 = gib[jg * 15 + ih0 * OW + qq];
                float v1 = gib[jg * 15 + (ih0 + 1) * OW + qq];
                vx = fmaf(fh, v1 - v0, v0);
            }
            if (qq + 4 < OW) {
                float v0 = gib[jg * 15 + ih0 * OW + qq + 4];
                float v1 = gib[jg * 15 + (ih0 + 1) * OW + qq + 4];
                vy = fmaf(fh, v1 - v0, v0);
            }
            if (G < 2) {
                float bv = bhh[g * 96 + jg];
                if (qq < OW) vx += bv;
                if (qq + 4 < OW) vy += bv;
            }
            gp[idx] = make_float2(__uint_as_float(cvt_tf32(vx)),
                                  __uint_as_float(cvt_tf32(vy)));
        }
    }
    __syncthreads();

    const float* gw = gbuf + warp * 96;                      // OW==1 path
    const float2* gpB = (OH == 1) ? (const float2*)gbuf
                                  : ((const float2*)gbuf + warp * 384);

    // bhh_n pairs for hn C-init: [eta][u] -> cols 16e+8u+2q, +1
    float bn[2][2][2];
    #pragma unroll
    for (int e = 0; e < 2; e++)
        #pragma unroll
        for (int u = 0; u < 2; u++) {
            bn[e][u][0] = bhh[g * 96 + 64 + 16 * e + 8 * u + 2 * q];
            bn[e][u][1] = bhh[g * 96 + 64 + 16 * e + 8 * u + 2 * q + 1];
        }

    const float* xrow = x + ((size_t)(b * 128 + g * 16)) * HW + h * 128;
    float* outrow = out + ((size_t)b * 256 + g) * HW + h * 128;
    float* xw = xsp + warp * 288;
    const int cch = lane >> 1, ph = lane & 1;
    const int slot = ((cch >> 3) * 4 + (cch & 3)) * 2 + ((cch >> 2) & 1);

    for (int tile = 0; tile < 8; tile++) {
        // ---- stage x (16px x 16ch), tf32, pair-permuted ----
        const float* src = xrow + (size_t)cch * HW + tile * 16 + 8 * ph;
        float4 va = *(const float4*)src;
        float4 vb = *(const float4*)(src + 4);
        float* dst = xw + (8 * ph) * 18 + slot;
        dst[0 * 18] = __uint_as_float(cvt_tf32(va.x));
        dst[1 * 18] = __uint_as_float(cvt_tf32(va.y));
        dst[2 * 18] = __uint_as_float(cvt_tf32(va.z));
        dst[3 * 18] = __uint_as_float(cvt_tf32(va.w));
        dst[4 * 18] = __uint_as_float(cvt_tf32(vb.x));
        dst[5 * 18] = __uint_as_float(cvt_tf32(vb.y));
        dst[6 * 18] = __uint_as_float(cvt_tf32(vb.z));
        dst[7 * 18] = __uint_as_float(cvt_tf32(vb.w));
        __syncwarp();

        // ---- A fragments (x) ----
        uint32_t A0[4], A1[4];
        {
            float2 lo = *(const float2*)(xw + p * 18 + (0 * 4 + q) * 2);
            float2 hi = *(const float2*)(xw + (p + 8) * 18 + (0 * 4 + q) * 2);
            A0[0] = __float_as_uint(lo.x); A0[1] = __float_as_uint(hi.x);
            A0[2] = __float_as_uint(lo.y); A0[3] = __float_as_uint(hi.y);
            lo = *(const float2*)(xw + p * 18 + (1 * 4 + q) * 2);
            hi = *(const float2*)(xw + (p + 8) * 18 + (1 * 4 + q) * 2);
            A1[0] = __float_as_uint(lo.x); A1[1] = __float_as_uint(hi.x);
            A1[2] = __float_as_uint(lo.y); A1[3] = __float_as_uint(hi.y);
        }

        // ---- coef fragments ----
        const int pxl0 = tile * 16 + p, pxl1 = pxl0 + 8;
        uint32_t AC0[4], AC1[4];
        if (OW > 1) {
            int j0e[2]; float fwe[2];
            const int pp[2] = {pxl0, pxl1};
            #pragma unroll
            for (int e = 0; e < 2; e++) {
                float s = (float)(pp[e] * (OW - 1)) * (1.0f / 127.0f);
                int jj = (int)s; if (jj > OW - 2) jj = OW - 2;
                j0e[e] = jj; fwe[e] = s - (float)jj;
            }
            AC0[0] = coef_tf32(q,     j0e[0], fwe[0]);
            AC0[1] = coef_tf32(q,     j0e[1], fwe[1]);
            AC0[2] = coef_tf32(q + 4, j0e[0], fwe[0]);
            AC0[3] = coef_tf32(q + 4, j0e[1], fwe[1]);
            if (KB == 2) {
                AC1[0] = coef_tf32(8 + q,     j0e[0], fwe[0]);
                AC1[1] = coef_tf32(8 + q,     j0e[1], fwe[1]);
                AC1[2] = coef_tf32(8 + q + 4, j0e[0], fwe[0]);
                AC1[3] = coef_tf32(8 + q + 4, j0e[1], fwe[1]);
            }
        }

        // ---- two j-halves ----
        #pragma unroll
        for (int eta = 0; eta < 2; eta++) {
            float aR[2][4], aZ[2][4], aN[2][4], aC[2][4], aG[2][4];
            #pragma unroll
            for (int u = 0; u < 2; u++) {
                const int cb = 16 * eta + 8 * u + p;     // col within gate
                const int jb = 16 * eta + 8 * u + p;     // growp j index
                float2 B;
                // r gate (cols +0)
                B = Wsm[q * 132 + cb];
                mma_init(aR[u], A0, __float_as_uint(B.x), __float_as_uint(B.y), 0.f, 0.f);
                B = Wsm[(4 + q) * 132 + cb];
                mma_acc(aR[u], A1, __float_as_uint(B.x), __float_as_uint(B.y));
                // z gate (cols +32)
                B = Wsm[q * 132 + 32 + cb];
                mma_init(aZ[u], A0, __float_as_uint(B.x), __float_as_uint(B.y), 0.f, 0.f);
                B = Wsm[(4 + q) * 132 + 32 + cb];
                mma_acc(aZ[u], A1, __float_as_uint(B.x), __float_as_uint(B.y));
                // hn gate (cols +64), C-init = bhh_n
                B = Wsm[q * 132 + 64 + cb];
                mma_init(aN[u], A0, __float_as_uint(B.x), __float_as_uint(B.y),
                         bn[eta][u][0], bn[eta][u][1]);
                B = Wsm[(4 + q) * 132 + 64 + cb];
                mma_acc(aN[u], A1, __float_as_uint(B.x), __float_as_uint(B.y));
                // cg (cols +96)
                B = Wsm[q * 132 + 96 + cb];
                mma_init(aC[u], A0, __float_as_uint(B.x), __float_as_uint(B.y), 0.f, 0.f);
                B = Wsm[(4 + q) * 132 + 96 + cb];
                mma_acc(aC[u], A1, __float_as_uint(B.x), __float_as_uint(B.y));
                if (OW > 1) {
                    // interp k-steps: r (G=0), z (G=1), gin (G=2)
                    float2 Bg;
                    Bg = gpB[(0 * 32 + jb) * 4 + q];
                    mma_acc(aR[u], AC0, __float_as_uint(Bg.x), __float_as_uint(Bg.y));
                    Bg = gpB[(1 * 32 + jb) * 4 + q];
                    mma_acc(aZ[u], AC0, __float_as_uint(Bg.x), __float_as_uint(Bg.y));
                    Bg = gpB[(2 * 32 + jb) * 4 + q];
                    mma_init(aG[u], AC0, __float_as_uint(Bg.x), __float_as_uint(Bg.y), 0.f, 0.f);
                    if (KB == 2) {
                        Bg = gpB[(384 + 0 * 32 + jb) * 4 + q - 384 * 3 + 384 * 3];  // bank1
                        Bg = gpB[((3 + 0) * 32 + jb) * 4 + q];
                        mma_acc(aR[u], AC1, __float_as_uint(Bg.x), __float_as_uint(Bg.y));
                        Bg = gpB[((3 + 1) * 32 + jb) * 4 + q];
                        mma_acc(aZ[u], AC1, __float_as_uint(Bg.x), __float_as_uint(Bg.y));
                        Bg = gpB[((3 + 2) * 32 + jb) * 4 + q];
                        mma_acc(aG[u], AC1, __float_as_uint(Bg.x), __float_as_uint(Bg.y));
                    }
                }
            }
            // ---- epilogue ----
            #pragma unroll
            for (int u = 0; u < 2; u++) {
                #pragma unroll
                for (int i = 0; i < 4; i++) {
                    const int e = i >> 1;
                    const int jl = 16 * eta + 8 * u + 2 * q + (i & 1);
                    const int px = (e == 0) ? pxl0 : pxl1;
                    float ar = aR[u][i], az = aZ[u][i];
                    float hn = aN[u][i], cg = aC[u][i];
                    float r, z, n;
                    if (OW == 1) {
                        r = sigfast(gw[jl] + ar);
                        z = sigfast(gw[32 + jl] + az);
                        n = tanhfast(fmaf(r, hn, gw[64 + jl]));
                    } else {
                        r = sigfast(ar);
                        z = sigfast(az);
                        n = tanhfast(fmaf(r, hn, aG[u][i]));
                    }
                    outrow[(size_t)(jl * 8) * HW + px] = fmaf(z, cg - n, n);
                }
            }
        }
        __syncwarp();   // protect xw WAR for next tile
    }
}

__global__ __launch_bounds__(256, 2) void main_kernel(
    const float* __restrict__ x, const float* __restrict__ Wcen,
    const float* __restrict__ bhh, float* __restrict__ out)
{
    __shared__ __align__(16) float2 Wsm[8 * 132];      // weight pairs (tf32 bits)
    __shared__ __align__(16) float xsp[8 * 288];       // per-warp staged x
    __shared__ __align__(16) float gbuf[6144];         // growp / gw (24KB)

    const int g = blockIdx.y;
    const int b = blockIdx.x >> 4;
    const int t = threadIdx.x;

    // build weight-pair matrix: cols 0-95 Wfold (r,z,n), 96-127 Wcen
    for (int idx = t; idx < 1024; idx += 256) {
        int qh = idx >> 7, col = idx & 127;
        int s = qh >> 2, qq = qh & 3;
        int k0 = 8 * s + qq, k1 = k0 + 4;
        float w0, w1;
        if (col < 96) {
            w0 = g_Wfold[(g * 96 + col) * 16 + k0];
            w1 = g_Wfold[(g * 96 + col) * 16 + k1];
        } else {
            w0 = Wcen[(g * 32 + col - 96) * 16 + k0];
            w1 = Wcen[(g * 32 + col - 96) * 16 + k1];
        }
        Wsm[qh * 132 + col] = make_float2(__uint_as_float(cvt_tf32(w0)),
                                          __uint_as_float(cvt_tf32(w1)));
    }
    // (__syncthreads happens inside run_group after gbuf build)

    switch (g >> 1) {
        case 0:  run_group<1, 11>(g, b, x, bhh, out, Wsm, xsp, gbuf); break;
        case 1:  run_group<11, 1>(g, b, x, bhh, out, Wsm, xsp, gbuf); break;
        case 2:  run_group<3, 5>(g, b, x, bhh, out, Wsm, xsp, gbuf); break;
        default: run_group<5, 3>(g, b, x, bhh, out, Wsm, xsp, gbuf); break;
    }
}

// ============================================================================
extern "C" void kernel_launch(void* const* d_in, const int* in_sizes, int n_in,
                              void* d_out, int out_size) {
    (void)in_sizes; (void)n_in; (void)out_size;
    const float* x    = (const float*)d_in[0];
    const float* Wcen = (const float*)d_in[1];
    const float* W0 = (const float*)d_in[2];  const float* b0 = (const float*)d_in[3];
    const float* W1 = (const float*)d_in[4];  const float* b1 = (const float*)d_in[5];
    const float* W2 = (const float*)d_in[6];  const float* b2 = (const float*)d_in[7];
    const float* W3 = (const float*)d_in[8];  const float* b3 = (const float*)d_in[9];
    const float* Wm  = (const float*)d_in[10];
    const float* Wih = (const float*)d_in[11];
    const float* Whh = (const float*)d_in[12];
    const float* bih = (const float*)d_in[13];
    const float* bhh = (const float*)d_in[14];
    float* out = (float*)d_out;

    pool_kernel<<<256, 128>>>(x);
    gi_fold_kernel<<<136, 256>>>(W0, b0, W1, b1, W2, b2, W3, b3,
                                 Wm, Wih, bih, Whh, Wcen);
    main_kernel<<<dim3(128, 8), 256>>>(x, Wcen, bhh, out);
}

// round 6
// speedup vs baseline: 1.1581x; 1.1581x over previous
#include <cuda_runtime.h>
#include <stdint.h>

#define HW 16384   // 128*128

// ---- device scratch ----
__device__ float g_pool[4 * 8 * 128 * 15];   // [br][b][c][pos]
__device__ float g_Wfold[8 * 96 * 16];       // Whh @ W_center per group
__device__ float g_Gi[8 * 8 * 96 * 15];      // [b][g][o][pos] (includes bih)

// ---- helpers ----
__device__ __forceinline__ float tanhfast(float x) {
    float y; asm("tanh.approx.f32 %0, %1;" : "=f"(y) : "f"(x)); return y;
}
__device__ __forceinline__ float sigfast(float x) {
    return fmaf(0.5f, tanhfast(0.5f * x), 0.5f);
}
__device__ __forceinline__ uint32_t cvt_tf32(float f) {
    uint32_t r; asm("cvt.rna.tf32.f32 %0, %1;" : "=r"(r) : "f"(f)); return r;
}
__device__ __forceinline__ void mma_acc(float d[4], const uint32_t a[4],
                                        uint32_t b0, uint32_t b1) {
    asm("mma.sync.aligned.m16n8k8.row.col.f32.tf32.tf32.f32 "
        "{%0,%1,%2,%3},{%4,%5,%6,%7},{%8,%9},{%0,%1,%2,%3};"
        : "+f"(d[0]), "+f"(d[1]), "+f"(d[2]), "+f"(d[3])
        : "r"(a[0]), "r"(a[1]), "r"(a[2]), "r"(a[3]), "r"(b0), "r"(b1));
}
__device__ __forceinline__ void mma_init(float d[4], const uint32_t a[4],
                                         uint32_t b0, uint32_t b1,
                                         float c0, float c1) {
    asm("mma.sync.aligned.m16n8k8.row.col.f32.tf32.tf32.f32 "
        "{%0,%1,%2,%3},{%4,%5,%6,%7},{%8,%9},{%10,%11,%10,%11};"
        : "=f"(d[0]), "=f"(d[1]), "=f"(d[2]), "=f"(d[3])
        : "r"(a[0]), "r"(a[1]), "r"(a[2]), "r"(a[3]), "r"(b0), "r"(b1),
          "f"(c0), "f"(c1));
}
__device__ __forceinline__ uint32_t coef_tf32(int pos, int j0, float fw) {
    float c = (pos == j0) ? (1.0f - fw) : ((pos == j0 + 1) ? fw : 0.0f);
    return cvt_tf32(c);
}

// ============================================================================
// K1: single-pass adaptive pools (R4 version). Block per (b,c), 128 threads =
// columns. Compile-time bin membership via full unroll.
// ============================================================================
__global__ __launch_bounds__(128) void pool_kernel(const float* __restrict__ x) {
    const int bc = blockIdx.x;
    const int b = bc >> 7, c = bc & 127;
    const float* tile = x + (size_t)bc * HW;
    const int t = threadIdx.x;

    float a0 = 0.0f;
    float a1[11], a2[3], a3[5];
    #pragma unroll
    for (int i = 0; i < 11; i++) a1[i] = 0.0f;
    #pragma unroll
    for (int i = 0; i < 3; i++) a2[i] = 0.0f;
    #pragma unroll
    for (int i = 0; i < 5; i++) a3[i] = 0.0f;

    #pragma unroll
    for (int h = 0; h < 128; h++) {
        float v = tile[h * 128 + t];
        a0 += v;
        {
            const int p = (h * 11) >> 7;
            a1[p] += v;
            if (p + 1 < 11 && h == ((p + 1) * 128) / 11 && (((p + 1) * 128) % 11) != 0)
                a1[p + 1] += v;
        }
        {
            const int p = (h * 3) >> 7;
            a2[p] += v;
            if (p + 1 < 3 && h == ((p + 1) * 128) / 3 && (((p + 1) * 128) % 3) != 0)
                a2[p + 1] += v;
        }
        {
            const int p = (h * 5) >> 7;
            a3[p] += v;
            if (p + 1 < 5 && h == ((p + 1) * 128) / 5 && (((p + 1) * 128) % 5) != 0)
                a3[p + 1] += v;
        }
    }

    __shared__ float cs[20][128];
    cs[0][t] = a0;
    #pragma unroll
    for (int i = 0; i < 11; i++) cs[1 + i][t] = a1[i];
    #pragma unroll
    for (int i = 0; i < 3; i++) cs[12 + i][t] = a2[i];
    #pragma unroll
    for (int i = 0; i < 5; i++) cs[15 + i][t] = a3[i];
    __syncthreads();

    const int warp = t >> 5, lane = t & 31;
    for (int oi = warp; oi < 52; oi += 4) {
        int br, pos, row, ws, we, hs, he;
        if (oi < 11) {
            br = 0; pos = oi; row = 0;
            hs = 0; he = 128;
            ws = (pos * 128) / 11; we = ((pos + 1) * 128 + 10) / 11;
        } else if (oi < 22) {
            br = 1; pos = oi - 11; row = 1 + pos;
            ws = 0; we = 128;
            hs = (pos * 128) / 11; he = ((pos + 1) * 128 + 10) / 11;
        } else if (oi < 37) {
            br = 2; pos = oi - 22;
            int i = pos / 5, jj = pos % 5;
            row = 12 + i;
            hs = (i * 128) / 3;  he = ((i + 1) * 128 + 2) / 3;
            ws = (jj * 128) / 5; we = ((jj + 1) * 128 + 4) / 5;
        } else {
            br = 3; pos = oi - 37;
            int i = pos / 3, jj = pos % 3;
            row = 15 + i;
            hs = (i * 128) / 5;  he = ((i + 1) * 128 + 4) / 5;
            ws = (jj * 128) / 3; we = ((jj + 1) * 128 + 2) / 3;
        }
        float s = 0.0f;
        for (int w = ws + lane; w < we; w += 32) s += cs[row][w];
        #pragma unroll
        for (int off = 16; off; off >>= 1) s += __shfl_down_sync(0xffffffffu, s, off);
        if (lane == 0)
            g_pool[((br * 8 + b) * 128 + c) * 15 + pos] =
                s / (float)((he - hs) * (we - ws));
    }
}

// ============================================================================
// K2: fused branch-linear + merge + Wih -> Gi (blocks 0..127, 2 per (b,g)),
//     plus Wfold = Whh @ W_center (blocks 128..135).
// ============================================================================
__global__ __launch_bounds__(256) void gi_fold_kernel(
    const float* __restrict__ W0, const float* __restrict__ b0,
    const float* __restrict__ W1, const float* __restrict__ b1,
    const float* __restrict__ W2, const float* __restrict__ b2,
    const float* __restrict__ W3, const float* __restrict__ b3,
    const float* __restrict__ Wm, const float* __restrict__ Wih,
    const float* __restrict__ bih,
    const float* __restrict__ Whh, const float* __restrict__ Wcen)
{
    const int blk = blockIdx.x;
    const int t = threadIdx.x;

    if (blk >= 128) {              // fold part
        int g = blk - 128;
        if (t < 96) {
            int o = t;
            #pragma unroll 4
            for (int i = 0; i < 16; i++) {
                float s = 0.0f;
                #pragma unroll
                for (int hh = 0; hh < 32; hh++)
                    s = fmaf(Whh[(g * 96 + o) * 32 + hh], Wcen[(g * 32 + hh) * 16 + i], s);
                g_Wfold[(g * 96 + o) * 16 + i] = s;
            }
        }
        return;
    }

    const int b = blk >> 4, g = (blk >> 1) & 7, half = blk & 1;
    const int br = g >> 1;
    const int GS = (br < 2) ? 11 : 15;
    const float* Ws[4] = {W0, W1, W2, W3};
    const float* bs[4] = {b0, b1, b2, b3};
    const float* W = Ws[br];
    const float* bias = bs[br];
    const int c0 = 64 * (g & 1);

    __shared__ float q[64 * 15];
    __shared__ float Bs[32 * 15];

    for (int idx = t; idx < 64 * GS; idx += 256) {
        int cc = idx / GS, m = idx - cc * GS;
        const float* src = g_pool + ((br * 8 + b) * 128 + c0 + cc) * 15;
        float s = bias[m];
        for (int d = 0; d < GS; d++) s = fmaf(W[m * GS + d], src[d], s);
        q[cc * GS + m] = s;
    }
    __syncthreads();

    for (int idx = t; idx < 32 * GS; idx += 256) {
        int f = idx / GS, pos = idx - f * GS;
        int i = 16 * g + (f >> 1), jm = f & 1;
        const float* qb = q + (4 * (f >> 1)) * GS + pos;
        float s = 0.0f;
        #pragma unroll
        for (int k = 0; k < 4; k++)
            s = fmaf(Wm[(i * 2 + jm) * 4 + k], qb[k * GS], s);
        Bs[f * GS + pos] = s;
    }
    __syncthreads();

    const int obase = half * 48;
    for (int idx = t; idx < 48 * GS; idx += 256) {
        int o = obase + idx / GS, pos = idx % GS;
        float s = bih[g * 96 + o];
        #pragma unroll 8
        for (int f = 0; f < 32; f++)
            s = fmaf(Wih[(g * 96 + o) * 32 + f], Bs[f * GS + pos], s);
        g_Gi[((b * 8 + g) * 96 + o) * 15 + pos] = s;
    }
}

// ============================================================================
// K3: main kernel. tf32 mma, w-interp folded into extra K-steps; 2 M-tiles
// (32 pixels) share each B-fragment load.
// grid (128, 8): g = blockIdx.y; b = blockIdx.x>>4; warp = one image row.
// ============================================================================
template<int OH, int OW>
__device__ __forceinline__ void run_group(
    int g, int b, const float* __restrict__ x, const float* __restrict__ bhh,
    float* __restrict__ out, const float2* Wsm, float* xsp, float* gbuf)
{
    constexpr int KB = (OW > 8) ? 2 : (OW > 1 ? 1 : 0);
    const int t = threadIdx.x;
    const int warp = t >> 5, lane = t & 31;
    const int p = lane >> 2, q = lane & 3;
    const int h = ((blockIdx.x & 15) << 3) + warp;
    const float* gib = g_Gi + (size_t)((b * 8 + g) * 96) * 15;

    // ---- build interp structures ----
    if (OW == 1) {
        float src = (float)(h * (OH - 1)) * (1.0f / 127.0f);
        int ih0 = (int)src; if (ih0 > OH - 2) ih0 = OH - 2;
        float fh = src - (float)ih0;
        for (int j = lane; j < 96; j += 32) {
            float v0 = gib[j * 15 + ih0];
            float v1 = gib[j * 15 + ih0 + 1];
            float v = fmaf(fh, v1 - v0, v0);
            if (j < 64) v += bhh[g * 96 + j];
            gbuf[warp * 96 + j] = v;
        }
    } else if (OH == 1) {
        float2* gp = (float2*)gbuf;
        for (int idx = t; idx < KB * 3 * 32 * 4; idx += 256) {
            int qq = idx & 3, j = (idx >> 2) & 31;
            int Gk = idx >> 7, G = Gk % 3, kb = Gk / 3;
            int jg = (G == 2) ? (64 + j) : (G * 32 + j);
            int pos0 = kb * 8 + qq, pos1 = pos0 + 4;
            float vx = 0.0f, vy = 0.0f;
            if (pos0 < OW) vx = gib[jg * 15 + pos0];
            if (pos1 < OW) vy = gib[jg * 15 + pos1];
            if (G < 2) {
                float bv = bhh[g * 96 + jg];
                if (pos0 < OW) vx += bv;
                if (pos1 < OW) vy += bv;
            }
            gp[idx] = make_float2(__uint_as_float(cvt_tf32(vx)),
                                  __uint_as_float(cvt_tf32(vy)));
        }
    } else {
        float2* gp = (float2*)gbuf + warp * 384;
        float src = (float)(h * (OH - 1)) * (1.0f / 127.0f);
        int ih0 = (int)src; if (ih0 > OH - 2) ih0 = OH - 2;
        float fh = src - (float)ih0;
        for (int idx = lane; idx < 3 * 32 * 4; idx += 32) {
            int qq = idx & 3, j = (idx >> 2) & 31, G = idx >> 7;
            int jg = (G == 2) ? (64 + j) : (G * 32 + j);
            float vx = 0.0f, vy = 0.0f;
            if (qq < OW) {
                float v0 = gib[jg * 15 + ih0 * OW + qq];
                float v1 = gib[jg * 15 + (ih0 + 1) * OW + qq];
                vx = fmaf(fh, v1 - v0, v0);
            }
            if (qq + 4 < OW) {
                float v0 = gib[jg * 15 + ih0 * OW + qq + 4];
                float v1 = gib[jg * 15 + (ih0 + 1) * OW + qq + 4];
                vy = fmaf(fh, v1 - v0, v0);
            }
            if (G < 2) {
                float bv = bhh[g * 96 + jg];
                if (qq < OW) vx += bv;
                if (qq + 4 < OW) vy += bv;
            }
            gp[idx] = make_float2(__uint_as_float(cvt_tf32(vx)),
                                  __uint_as_float(cvt_tf32(vy)));
        }
    }
    __syncthreads();

    const float2* gpB = (OH == 1) ? (const float2*)gbuf
                                  : ((const float2*)gbuf + warp * 384);

    // OW==1: hoist row-constant gi values into registers
    float gvr[2][2][2], gvz[2][2][2], gvn[2][2][2];
    if (OW == 1) {
        const float* gw = gbuf + warp * 96;
        #pragma unroll
        for (int e = 0; e < 2; e++)
            #pragma unroll
            for (int u = 0; u < 2; u++)
                #pragma unroll
                for (int d = 0; d < 2; d++) {
                    int jl = 16 * e + 8 * u + 2 * q + d;
                    gvr[e][u][d] = gw[jl];
                    gvz[e][u][d] = gw[32 + jl];
                    gvn[e][u][d] = gw[64 + jl];
                }
    }

    // bhh_n pairs for hn C-init
    float bn[2][2][2];
    #pragma unroll
    for (int e = 0; e < 2; e++)
        #pragma unroll
        for (int u = 0; u < 2; u++) {
            bn[e][u][0] = bhh[g * 96 + 64 + 16 * e + 8 * u + 2 * q];
            bn[e][u][1] = bhh[g * 96 + 64 + 16 * e + 8 * u + 2 * q + 1];
        }

    const float* xrow = x + ((size_t)(b * 128 + g * 16)) * HW + h * 128;
    float* outrow = out + ((size_t)b * 256 + g) * HW + h * 128;
    float* xw = xsp + warp * 288;
    const int cch = lane >> 1, ph = lane & 1;
    const int slot = ((cch >> 3) * 4 + (cch & 3)) * 2 + ((cch >> 2) & 1);

    for (int tile2 = 0; tile2 < 4; tile2++) {
        const int pxbase = tile2 * 32;

        // ---- stage both 16px tiles sequentially; keep A frags in regs ----
        uint32_t A[2][2][4];
        #pragma unroll
        for (int m = 0; m < 2; m++) {
            const float* src = xrow + (size_t)cch * HW + pxbase + m * 16 + 8 * ph;
            float4 va = *(const float4*)src;
            float4 vb = *(const float4*)(src + 4);
            float* dst = xw + (8 * ph) * 18 + slot;
            dst[0 * 18] = __uint_as_float(cvt_tf32(va.x));
            dst[1 * 18] = __uint_as_float(cvt_tf32(va.y));
            dst[2 * 18] = __uint_as_float(cvt_tf32(va.z));
            dst[3 * 18] = __uint_as_float(cvt_tf32(va.w));
            dst[4 * 18] = __uint_as_float(cvt_tf32(vb.x));
            dst[5 * 18] = __uint_as_float(cvt_tf32(vb.y));
            dst[6 * 18] = __uint_as_float(cvt_tf32(vb.z));
            dst[7 * 18] = __uint_as_float(cvt_tf32(vb.w));
            __syncwarp();
            #pragma unroll
            for (int s = 0; s < 2; s++) {
                float2 lo = *(const float2*)(xw + p * 18 + (s * 4 + q) * 2);
                float2 hi = *(const float2*)(xw + (p + 8) * 18 + (s * 4 + q) * 2);
                A[m][s][0] = __float_as_uint(lo.x);
                A[m][s][1] = __float_as_uint(hi.x);
                A[m][s][2] = __float_as_uint(lo.y);
                A[m][s][3] = __float_as_uint(hi.y);
            }
            __syncwarp();
        }

        // ---- coef fragments ----
        uint32_t AC0[2][4], AC1[2][4];
        if (OW > 1) {
            #pragma unroll
            for (int m = 0; m < 2; m++) {
                int j0e[2]; float fwe[2];
                const int pp[2] = {pxbase + m * 16 + p, pxbase + m * 16 + p + 8};
                #pragma unroll
                for (int e = 0; e < 2; e++) {
                    float s = (float)(pp[e] * (OW - 1)) * (1.0f / 127.0f);
                    int jj = (int)s; if (jj > OW - 2) jj = OW - 2;
                    j0e[e] = jj; fwe[e] = s - (float)jj;
                }
                AC0[m][0] = coef_tf32(q,     j0e[0], fwe[0]);
                AC0[m][1] = coef_tf32(q,     j0e[1], fwe[1]);
                AC0[m][2] = coef_tf32(q + 4, j0e[0], fwe[0]);
                AC0[m][3] = coef_tf32(q + 4, j0e[1], fwe[1]);
                if (KB == 2) {
                    AC1[m][0] = coef_tf32(8 + q,     j0e[0], fwe[0]);
                    AC1[m][1] = coef_tf32(8 + q,     j0e[1], fwe[1]);
                    AC1[m][2] = coef_tf32(8 + q + 4, j0e[0], fwe[0]);
                    AC1[m][3] = coef_tf32(8 + q + 4, j0e[1], fwe[1]);
                }
            }
        }

        // ---- 4 (eta,u) combos; B loaded once per combo, used by both tiles ----
        #pragma unroll
        for (int eta = 0; eta < 2; eta++) {
            #pragma unroll
            for (int u = 0; u < 2; u++) {
                const int cb = 16 * eta + 8 * u + p;
                float2 Br0 = Wsm[q * 132 + cb];
                float2 Br1 = Wsm[(4 + q) * 132 + cb];
                float2 Bz0 = Wsm[q * 132 + 32 + cb];
                float2 Bz1 = Wsm[(4 + q) * 132 + 32 + cb];
                float2 Bn0 = Wsm[q * 132 + 64 + cb];
                float2 Bn1 = Wsm[(4 + q) * 132 + 64 + cb];
                float2 Bc0 = Wsm[q * 132 + 96 + cb];
                float2 Bc1 = Wsm[(4 + q) * 132 + 96 + cb];
                float2 Gr0, Gz0, Gn0, Gr1, Gz1, Gn1;
                if (OW > 1) {
                    Gr0 = gpB[(0 * 32 + cb) * 4 + q];
                    Gz0 = gpB[(1 * 32 + cb) * 4 + q];
                    Gn0 = gpB[(2 * 32 + cb) * 4 + q];
                    if (KB == 2) {
                        Gr1 = gpB[(3 * 32 + cb) * 4 + q];
                        Gz1 = gpB[(4 * 32 + cb) * 4 + q];
                        Gn1 = gpB[(5 * 32 + cb) * 4 + q];
                    }
                }

                float aR[2][4], aZ[2][4], aN[2][4], aC[2][4], aG[2][4];
                #pragma unroll
                for (int m = 0; m < 2; m++) {
                    mma_init(aR[m], A[m][0], __float_as_uint(Br0.x), __float_as_uint(Br0.y), 0.f, 0.f);
                    mma_acc (aR[m], A[m][1], __float_as_uint(Br1.x), __float_as_uint(Br1.y));
                    mma_init(aZ[m], A[m][0], __float_as_uint(Bz0.x), __float_as_uint(Bz0.y), 0.f, 0.f);
                    mma_acc (aZ[m], A[m][1], __float_as_uint(Bz1.x), __float_as_uint(Bz1.y));
                    mma_init(aN[m], A[m][0], __float_as_uint(Bn0.x), __float_as_uint(Bn0.y),
                             bn[eta][u][0], bn[eta][u][1]);
                    mma_acc (aN[m], A[m][1], __float_as_uint(Bn1.x), __float_as_uint(Bn1.y));
                    mma_init(aC[m], A[m][0], __float_as_uint(Bc0.x), __float_as_uint(Bc0.y), 0.f, 0.f);
                    mma_acc (aC[m], A[m][1], __float_as_uint(Bc1.x), __float_as_uint(Bc1.y));
                    if (OW > 1) {
                        mma_acc (aR[m], AC0[m], __float_as_uint(Gr0.x), __float_as_uint(Gr0.y));
                        mma_acc (aZ[m], AC0[m], __float_as_uint(Gz0.x), __float_as_uint(Gz0.y));
                        mma_init(aG[m], AC0[m], __float_as_uint(Gn0.x), __float_as_uint(Gn0.y), 0.f, 0.f);
                        if (KB == 2) {
                            mma_acc(aR[m], AC1[m], __float_as_uint(Gr1.x), __float_as_uint(Gr1.y));
                            mma_acc(aZ[m], AC1[m], __float_as_uint(Gz1.x), __float_as_uint(Gz1.y));
                            mma_acc(aG[m], AC1[m], __float_as_uint(Gn1.x), __float_as_uint(Gn1.y));
                        }
                    }
                }

                // ---- epilogue ----
                #pragma unroll
                for (int m = 0; m < 2; m++) {
                    #pragma unroll
                    for (int i = 0; i < 4; i++) {
                        const int d = i & 1;
                        const int jl = 16 * eta + 8 * u + 2 * q + d;
                        const int px = pxbase + m * 16 + p + (i >> 1) * 8;
                        float r, z, n;
                        if (OW == 1) {
                            r = sigfast(gvr[eta][u][d] + aR[m][i]);
                            z = sigfast(gvz[eta][u][d] + aZ[m][i]);
                            n = tanhfast(fmaf(r, aN[m][i], gvn[eta][u][d]));
                        } else {
                            r = sigfast(aR[m][i]);
                            z = sigfast(aZ[m][i]);
                            n = tanhfast(fmaf(r, aN[m][i], aG[m][i]));
                        }
                        outrow[(size_t)(jl * 8) * HW + px] = fmaf(z, aC[m][i] - n, n);
                    }
                }
            }
        }
        __syncwarp();   // protect xw WAR for next tile2
    }
}

__global__ __launch_bounds__(256, 2) void main_kernel(
    const float* __restrict__ x, const float* __restrict__ Wcen,
    const float* __restrict__ bhh, float* __restrict__ out)
{
    __shared__ __align__(16) float2 Wsm[8 * 132];      // weight pairs (tf32 bits)
    __shared__ __align__(16) float xsp[8 * 288];       // per-warp staged x
    __shared__ __align__(16) float gbuf[6144];         // growp / gw

    const int g = blockIdx.y;
    const int b = blockIdx.x >> 4;
    const int t = threadIdx.x;

    // build weight-pair matrix: cols 0-95 Wfold (r,z,n), 96-127 Wcen
    for (int idx = t; idx < 1024; idx += 256) {
        int qh = idx >> 7, col = idx & 127;
        int s = qh >> 2, qq = qh & 3;
        int k0 = 8 * s + qq, k1 = k0 + 4;
        float w0, w1;
        if (col < 96) {
            w0 = g_Wfold[(g * 96 + col) * 16 + k0];
            w1 = g_Wfold[(g * 96 + col) * 16 + k1];
        } else {
            w0 = Wcen[(g * 32 + col - 96) * 16 + k0];
            w1 = Wcen[(g * 32 + col - 96) * 16 + k1];
        }
        Wsm[qh * 132 + col] = make_float2(__uint_as_float(cvt_tf32(w0)),
                                          __uint_as_float(cvt_tf32(w1)));
    }
    // (__syncthreads happens inside run_group after gbuf build)

    switch (g >> 1) {
        case 0:  run_group<1, 11>(g, b, x, bhh, out, Wsm, xsp, gbuf); break;
        case 1:  run_group<11, 1>(g, b, x, bhh, out, Wsm, xsp, gbuf); break;
        case 2:  run_group<3, 5>(g, b, x, bhh, out, Wsm, xsp, gbuf); break;
        default: run_group<5, 3>(g, b, x, bhh, out, Wsm, xsp, gbuf); break;
    }
}

// ============================================================================
extern "C" void kernel_launch(void* const* d_in, const int* in_sizes, int n_in,
                              void* d_out, int out_size) {
    (void)in_sizes; (void)n_in; (void)out_size;
    const float* x    = (const float*)d_in[0];
    const float* Wcen = (const float*)d_in[1];
    const float* W0 = (const float*)d_in[2];  const float* b0 = (const float*)d_in[3];
    const float* W1 = (const float*)d_in[4];  const float* b1 = (const float*)d_in[5];
    const float* W2 = (const float*)d_in[6];  const float* b2 = (const float*)d_in[7];
    const float* W3 = (const float*)d_in[8];  const float* b3 = (const float*)d_in[9];
    const float* Wm  = (const float*)d_in[10];
    const float* Wih = (const float*)d_in[11];
    const float* Whh = (const float*)d_in[12];
    const float* bih = (const float*)d_in[13];
    const float* bhh = (const float*)d_in[14];
    float* out = (float*)d_out;

    pool_kernel<<<1024, 128>>>(x);
    gi_fold_kernel<<<136, 256>>>(W0, b0, W1, b1, W2, b2, W3, b3,
                                 Wm, Wih, bih, Whh, Wcen);
    main_kernel<<<dim3(128, 8), 256>>>(x, Wcen, bhh, out);
}

// round 8
// speedup vs baseline: 1.3493x; 1.1651x over previous
#include <cuda_runtime.h>
#include <stdint.h>

#define HW 16384   // 128*128

// ---- device scratch ----
__device__ float g_pool[4 * 8 * 128 * 15];   // [br][b][c][pos]
__device__ float g_Wfold[8 * 96 * 16];       // Whh @ W_center per group
__device__ float g_Gi[8 * 8 * 96 * 15];      // [b][g][o][pos] (includes bih)

// ---- helpers ----
__device__ __forceinline__ float tanhfast(float x) {
    float y; asm("tanh.approx.f32 %0, %1;" : "=f"(y) : "f"(x)); return y;
}
__device__ __forceinline__ float sigfast(float x) {
    return fmaf(0.5f, tanhfast(0.5f * x), 0.5f);
}
// pack two f32 into f16x2: lo = first arg, hi = second arg
__device__ __forceinline__ uint32_t pack_h2(float lo, float hi) {
    uint32_t r; asm("cvt.rn.f16x2.f32 %0, %1, %2;" : "=r"(r) : "f"(hi), "f"(lo));
    return r;
}
__device__ __forceinline__ void mmaf16_acc(float d[4], const uint32_t a[4],
                                           uint32_t b0, uint32_t b1) {
    asm("mma.sync.aligned.m16n8k16.row.col.f32.f16.f16.f32 "
        "{%0,%1,%2,%3},{%4,%5,%6,%7},{%8,%9},{%0,%1,%2,%3};"
        : "+f"(d[0]), "+f"(d[1]), "+f"(d[2]), "+f"(d[3])
        : "r"(a[0]), "r"(a[1]), "r"(a[2]), "r"(a[3]), "r"(b0), "r"(b1));
}
__device__ __forceinline__ void mmaf16_init(float d[4], const uint32_t a[4],
                                            uint32_t b0, uint32_t b1,
                                            float c0, float c1) {
    asm("mma.sync.aligned.m16n8k16.row.col.f32.f16.f16.f32 "
        "{%0,%1,%2,%3},{%4,%5,%6,%7},{%8,%9},{%10,%11,%10,%11};"
        : "=f"(d[0]), "=f"(d[1]), "=f"(d[2]), "=f"(d[3])
        : "r"(a[0]), "r"(a[1]), "r"(a[2]), "r"(a[3]), "r"(b0), "r"(b1),
          "f"(c0), "f"(c1));
}
__device__ __forceinline__ float coef_f(int pos, int j0, float fw) {
    return (pos == j0) ? (1.0f - fw) : ((pos == j0 + 1) ? fw : 0.0f);
}

// ============================================================================
// K1: adaptive pools. Block per (b,c), 256 threads = 2 per column (h halves).
// Each half fully unrolled (compile-time bin indices); halves combined in the
// smem reduction. No atomics, no scratch zeroing.
// ============================================================================
#define POOL_BODY(hconst)                                                      \
    {                                                                          \
        const int hv = (hconst);                                               \
        float v = tile[hv * 128 + col];                                        \
        a0 += v;                                                               \
        {                                                                      \
            const int pb = (hv * 11) >> 7;                                     \
            a1[pb] += v;                                                       \
            if (pb + 1 < 11 && hv == ((pb + 1) * 128) / 11 &&                  \
                (((pb + 1) * 128) % 11) != 0) a1[pb + 1] += v;                 \
        }                                                                      \
        {                                                                      \
            const int pb = (hv * 3) >> 7;                                      \
            a2[pb] += v;                                                       \
            if (pb + 1 < 3 && hv == ((pb + 1) * 128) / 3 &&                    \
                (((pb + 1) * 128) % 3) != 0) a2[pb + 1] += v;                  \
        }                                                                      \
        {                                                                      \
            const int pb = (hv * 5) >> 7;                                      \
            a3[pb] += v;                                                       \
            if (pb + 1 < 5 && hv == ((pb + 1) * 128) / 5 &&                    \
                (((pb + 1) * 128) % 5) != 0) a3[pb + 1] += v;                  \
        }                                                                      \
    }

__global__ __launch_bounds__(256) void pool_kernel(const float* __restrict__ x) {
    const int bc = blockIdx.x;
    const int b = bc >> 7, c = bc & 127;
    const float* tile = x + (size_t)bc * HW;
    const int col = threadIdx.x & 127, hh = threadIdx.x >> 7;

    float a0 = 0.0f;
    float a1[11], a2[3], a3[5];
    #pragma unroll
    for (int i = 0; i < 11; i++) a1[i] = 0.0f;
    #pragma unroll
    for (int i = 0; i < 3; i++) a2[i] = 0.0f;
    #pragma unroll
    for (int i = 0; i < 5; i++) a3[i] = 0.0f;

    if (hh == 0) {
        #pragma unroll
        for (int h = 0; h < 64; h++) POOL_BODY(h)
    } else {
        #pragma unroll
        for (int h = 64; h < 128; h++) POOL_BODY(h)
    }

    __shared__ float cs[2][20][128];
    cs[hh][0][col] = a0;
    #pragma unroll
    for (int i = 0; i < 11; i++) cs[hh][1 + i][col] = a1[i];
    #pragma unroll
    for (int i = 0; i < 3; i++) cs[hh][12 + i][col] = a2[i];
    #pragma unroll
    for (int i = 0; i < 5; i++) cs[hh][15 + i][col] = a3[i];
    __syncthreads();

    const int warp = threadIdx.x >> 5, lane = threadIdx.x & 31;
    for (int oi = warp; oi < 52; oi += 8) {
        int br, pos, row, ws, we, hs, he;
        if (oi < 11) {
            br = 0; pos = oi; row = 0;
            hs = 0; he = 128;
            ws = (pos * 128) / 11; we = ((pos + 1) * 128 + 10) / 11;
        } else if (oi < 22) {
            br = 1; pos = oi - 11; row = 1 + pos;
            ws = 0; we = 128;
            hs = (pos * 128) / 11; he = ((pos + 1) * 128 + 10) / 11;
        } else if (oi < 37) {
            br = 2; pos = oi - 22;
            int i = pos / 5, jj = pos % 5;
            row = 12 + i;
            hs = (i * 128) / 3;  he = ((i + 1) * 128 + 2) / 3;
            ws = (jj * 128) / 5; we = ((jj + 1) * 128 + 4) / 5;
        } else {
            br = 3; pos = oi - 37;
            int i = pos / 3, jj = pos % 3;
            row = 15 + i;
            hs = (i * 128) / 5;  he = ((i + 1) * 128 + 4) / 5;
            ws = (jj * 128) / 3; we = ((jj + 1) * 128 + 2) / 3;
        }
        float s = 0.0f;
        for (int w = ws + lane; w < we; w += 32)
            s += cs[0][row][w] + cs[1][row][w];
        #pragma unroll
        for (int off = 16; off; off >>= 1) s += __shfl_down_sync(0xffffffffu, s, off);
        if (lane == 0)
            g_pool[((br * 8 + b) * 128 + c) * 15 + pos] =
                s / (float)((he - hs) * (we - ws));
    }
}

// ============================================================================
// K2: fused branch-linear + merge + Wih -> Gi (blocks 0..127, 2 per (b,g)),
//     plus Wfold = Whh @ W_center (blocks 128..135).
// ============================================================================
__global__ __launch_bounds__(256) void gi_fold_kernel(
    const float* __restrict__ W0, const float* __restrict__ b0,
    const float* __restrict__ W1, const float* __restrict__ b1,
    const float* __restrict__ W2, const float* __restrict__ b2,
    const float* __restrict__ W3, const float* __restrict__ b3,
    const float* __restrict__ Wm, const float* __restrict__ Wih,
    const float* __restrict__ bih,
    const float* __restrict__ Whh, const float* __restrict__ Wcen)
{
    const int blk = blockIdx.x;
    const int t = threadIdx.x;

    if (blk >= 128) {              // fold part
        int g = blk - 128;
        if (t < 96) {
            int o = t;
            #pragma unroll 4
            for (int i = 0; i < 16; i++) {
                float s = 0.0f;
                #pragma unroll
                for (int hh = 0; hh < 32; hh++)
                    s = fmaf(Whh[(g * 96 + o) * 32 + hh], Wcen[(g * 32 + hh) * 16 + i], s);
                g_Wfold[(g * 96 + o) * 16 + i] = s;
            }
        }
        return;
    }

    const int b = blk >> 4, g = (blk >> 1) & 7, half = blk & 1;
    const int br = g >> 1;
    const int GS = (br < 2) ? 11 : 15;
    const float* Ws[4] = {W0, W1, W2, W3};
    const float* bs[4] = {b0, b1, b2, b3};
    const float* W = Ws[br];
    const float* bias = bs[br];
    const int c0 = 64 * (g & 1);

    __shared__ float q[64 * 15];
    __shared__ float Bs[32 * 15];

    for (int idx = t; idx < 64 * GS; idx += 256) {
        int cc = idx / GS, m = idx - cc * GS;
        const float* src = g_pool + ((br * 8 + b) * 128 + c0 + cc) * 15;
        float s = bias[m];
        for (int d = 0; d < GS; d++) s = fmaf(W[m * GS + d], src[d], s);
        q[cc * GS + m] = s;
    }
    __syncthreads();

    for (int idx = t; idx < 32 * GS; idx += 256) {
        int f = idx / GS, pos = idx - f * GS;
        int i = 16 * g + (f >> 1), jm = f & 1;
        const float* qb = q + (4 * (f >> 1)) * GS + pos;
        float s = 0.0f;
        #pragma unroll
        for (int k = 0; k < 4; k++)
            s = fmaf(Wm[(i * 2 + jm) * 4 + k], qb[k * GS], s);
        Bs[f * GS + pos] = s;
    }
    __syncthreads();

    const int obase = half * 48;
    for (int idx = t; idx < 48 * GS; idx += 256) {
        int o = obase + idx / GS, pos = idx % GS;
        float s = bih[g * 96 + o];
        #pragma unroll 8
        for (int f = 0; f < 32; f++)
            s = fmaf(Wih[(g * 96 + o) * 32 + f], Bs[f * GS + pos], s);
        g_Gi[((b * 8 + g) * 96 + o) * 15 + pos] = s;
    }
}

// ============================================================================
// K3: main kernel. fp16 m16n8k16 mma; k16 covers all 16 input channels in one
// mma per gate; interp (w-direction bilinear) folded as one more k16 mma with
// coefficient A-fragments. No smem x-staging: direct per-thread LDG of the
// 8 scalars each A-fragment needs.
// grid (256, 8): g = blockIdx.y; b = blockIdx.x>>5; warp = one image row.
// ============================================================================
template<int OH, int OW>
__device__ __forceinline__ void run_group(
    int g, int b, const float* __restrict__ x, const float* __restrict__ bhh,
    float* __restrict__ out, const uint2* Wh, char* gbuf_raw)
{
    const int t = threadIdx.x;
    const int warp = t >> 5, lane = t & 31;
    const int p = lane >> 2, q = lane & 3;
    const int h = ((blockIdx.x & 31) << 2) + warp;
    const float* gib = g_Gi + (size_t)((b * 8 + g) * 96) * 15;

    // ---- build interp structures ----
    if (OW == 1) {
        float* gw = (float*)gbuf_raw + warp * 96;
        float src = (float)(h * (OH - 1)) * (1.0f / 127.0f);
        int ih0 = (int)src; if (ih0 > OH - 2) ih0 = OH - 2;
        float fh = src - (float)ih0;
        for (int j = lane; j < 96; j += 32) {
            float v0 = gib[j * 15 + ih0];
            float v1 = gib[j * 15 + ih0 + 1];
            float v = fmaf(fh, v1 - v0, v0);
            if (j < 64) v += bhh[g * 96 + j];
            gw[j] = v;
        }
    } else if (OH == 1) {
        // shared Gh: [Gq = G*4+q][j] uint2 = f16x2 pairs for k = {2q,2q+1},{2q+8,2q+9}
        uint2* gp = (uint2*)gbuf_raw;
        for (int idx = t; idx < 384; idx += 128) {
            int j = idx & 31, Gq = idx >> 5;
            int G = Gq >> 2, qq = Gq & 3;
            int jg = G * 32 + j;
            float bv = (G < 2) ? bhh[g * 96 + jg] : 0.0f;
            float v0 = (2 * qq     < OW) ? gib[jg * 15 + 2 * qq]     + bv : 0.0f;
            float v1 = (2 * qq + 1 < OW) ? gib[jg * 15 + 2 * qq + 1] + bv : 0.0f;
            float v2 = (2 * qq + 8 < OW) ? gib[jg * 15 + 2 * qq + 8] + bv : 0.0f;
            float v3 = (2 * qq + 9 < OW) ? gib[jg * 15 + 2 * qq + 9] + bv : 0.0f;
            gp[Gq * 36 + j] = make_uint2(pack_h2(v0, v1), pack_h2(v2, v3));
        }
    } else {
        // per-warp Gh, h-interpolated
        uint2* gp = (uint2*)gbuf_raw + warp * 432;
        float src = (float)(h * (OH - 1)) * (1.0f / 127.0f);
        int ih0 = (int)src; if (ih0 > OH - 2) ih0 = OH - 2;
        float fh = src - (float)ih0;
        for (int idx = lane; idx < 384; idx += 32) {
            int j = idx & 31, Gq = idx >> 5;
            int G = Gq >> 2, qq = Gq & 3;
            int jg = G * 32 + j;
            float bv = (G < 2) ? bhh[g * 96 + jg] : 0.0f;
            float vv[4];
            const int pos[4] = {2 * qq, 2 * qq + 1, 2 * qq + 8, 2 * qq + 9};
            #pragma unroll
            for (int k2 = 0; k2 < 4; k2++) {
                float vx = 0.0f;
                if (pos[k2] < OW) {
                    float v0 = gib[jg * 15 + ih0 * OW + pos[k2]];
                    float v1 = gib[jg * 15 + (ih0 + 1) * OW + pos[k2]];
                    vx = fmaf(fh, v1 - v0, v0) + bv;
                }
                vv[k2] = vx;
            }
            gp[Gq * 36 + j] = make_uint2(pack_h2(vv[0], vv[1]), pack_h2(vv[2], vv[3]));
        }
    }
    __syncthreads();

    const uint2* gpB = (OH == 1) ? (const uint2*)gbuf_raw
                                 : ((const uint2*)gbuf_raw + warp * 432);

    // OW==1: row-constant gi values in registers
    float gvr[2][2][2], gvz[2][2][2], gvn[2][2][2];
    if (OW == 1) {
        const float* gw = (const float*)gbuf_raw + warp * 96;
        #pragma unroll
        for (int e = 0; e < 2; e++)
            #pragma unroll
            for (int u = 0; u < 2; u++)
                #pragma unroll
                for (int d = 0; d < 2; d++) {
                    int jl = 16 * e + 8 * u + 2 * q + d;
                    gvr[e][u][d] = gw[jl];
                    gvz[e][u][d] = gw[32 + jl];
                    gvn[e][u][d] = gw[64 + jl];
                }
    }

    // bhh_n pairs for hn C-init
    float bn[2][2][2];
    #pragma unroll
    for (int e = 0; e < 2; e++)
        #pragma unroll
        for (int u = 0; u < 2; u++) {
            bn[e][u][0] = bhh[g * 96 + 64 + 16 * e + 8 * u + 2 * q];
            bn[e][u][1] = bhh[g * 96 + 64 + 16 * e + 8 * u + 2 * q + 1];
        }

    const float* xrow = x + ((size_t)(b * 128 + g * 16)) * HW + h * 128;
    float* outrow = out + ((size_t)b * 256 + g) * HW + h * 128;
    const float* xc0 = xrow + (size_t)(2 * q) * HW;
    const float* xc1 = xrow + (size_t)(2 * q + 1) * HW;
    const float* xc2 = xrow + (size_t)(2 * q + 8) * HW;
    const float* xc3 = xrow + (size_t)(2 * q + 9) * HW;

    for (int tile2 = 0; tile2 < 4; tile2++) {
        const int pxbase = tile2 * 32;

        // ---- A fragments: direct loads, fp16-packed ----
        uint32_t A[2][4];
        #pragma unroll
        for (int m = 0; m < 2; m++) {
            const int p0 = pxbase + m * 16 + p;
            float x00 = xc0[p0],     x10 = xc1[p0];
            float x01 = xc0[p0 + 8], x11 = xc1[p0 + 8];
            float x20 = xc2[p0],     x30 = xc3[p0];
            float x21 = xc2[p0 + 8], x31 = xc3[p0 + 8];
            A[m][0] = pack_h2(x00, x10);
            A[m][1] = pack_h2(x01, x11);
            A[m][2] = pack_h2(x20, x30);
            A[m][3] = pack_h2(x21, x31);
        }

        // ---- coef fragments ----
        uint32_t AC[2][4];
        if (OW > 1) {
            #pragma unroll
            for (int m = 0; m < 2; m++) {
                const int pe0 = pxbase + m * 16 + p, pe1 = pe0 + 8;
                float s0 = (float)(pe0 * (OW - 1)) * (1.0f / 127.0f);
                int j00 = (int)s0; if (j00 > OW - 2) j00 = OW - 2;
                float f0 = s0 - (float)j00;
                float s1 = (float)(pe1 * (OW - 1)) * (1.0f / 127.0f);
                int j01 = (int)s1; if (j01 > OW - 2) j01 = OW - 2;
                float f1 = s1 - (float)j01;
                AC[m][0] = pack_h2(coef_f(2 * q, j00, f0),     coef_f(2 * q + 1, j00, f0));
                AC[m][1] = pack_h2(coef_f(2 * q, j01, f1),     coef_f(2 * q + 1, j01, f1));
                AC[m][2] = pack_h2(coef_f(2 * q + 8, j00, f0), coef_f(2 * q + 9, j00, f0));
                AC[m][3] = pack_h2(coef_f(2 * q + 8, j01, f1), coef_f(2 * q + 9, j01, f1));
            }
        }

        #pragma unroll
        for (int eta = 0; eta < 2; eta++) {
            #pragma unroll
            for (int u = 0; u < 2; u++) {
                const int cb = 16 * eta + 8 * u + p;
                uint2 wr = Wh[q * 132 + cb];
                uint2 wz = Wh[q * 132 + 32 + cb];
                uint2 wn = Wh[q * 132 + 64 + cb];
                uint2 wc = Wh[q * 132 + 96 + cb];
                uint2 grB, gzB, gnB;
                if (OW > 1) {
                    grB = gpB[(0 * 4 + q) * 36 + cb];
                    gzB = gpB[(1 * 4 + q) * 36 + cb];
                    gnB = gpB[(2 * 4 + q) * 36 + cb];
                }

                #pragma unroll
                for (int m = 0; m < 2; m++) {
                    float aR[4], aZ[4], aN[4], aC[4], aG[4];
                    mmaf16_init(aR, A[m], wr.x, wr.y, 0.f, 0.f);
                    mmaf16_init(aZ, A[m], wz.x, wz.y, 0.f, 0.f);
                    mmaf16_init(aN, A[m], wn.x, wn.y, bn[eta][u][0], bn[eta][u][1]);
                    mmaf16_init(aC, A[m], wc.x, wc.y, 0.f, 0.f);
                    if (OW > 1) {
                        mmaf16_acc(aR, AC[m], grB.x, grB.y);
                        mmaf16_acc(aZ, AC[m], gzB.x, gzB.y);
                        mmaf16_init(aG, AC[m], gnB.x, gnB.y, 0.f, 0.f);
                    }

                    #pragma unroll
                    for (int i = 0; i < 4; i++) {
                        const int d = i & 1, e = i >> 1;
                        const int jl = 16 * eta + 8 * u + 2 * q + d;
                        const int px = pxbase + m * 16 + p + e * 8;
                        float r, z, n;
                        if (OW == 1) {
                            r = sigfast(gvr[eta][u][d] + aR[i]);
                            z = sigfast(gvz[eta][u][d] + aZ[i]);
                            n = tanhfast(fmaf(r, aN[i], gvn[eta][u][d]));
                        } else {
                            r = sigfast(aR[i]);
                            z = sigfast(aZ[i]);
                            n = tanhfast(fmaf(r, aN[i], aG[i]));
                        }
                        outrow[(size_t)(jl * 8) * HW + px] = fmaf(z, aC[i] - n, n);
                    }
                }
            }
        }
    }
}

__global__ __launch_bounds__(128, 5) void main_kernel(
    const float* __restrict__ x, const float* __restrict__ Wcen,
    const float* __restrict__ bhh, float* __restrict__ out)
{
    __shared__ __align__(16) uint2 Wh[4 * 132];        // fp16 weight k-pairs
    __shared__ __align__(16) char gbuf_raw[4 * 432 * 8];  // per-warp Gh / gw

    const int g = blockIdx.y;
    const int b = blockIdx.x >> 5;
    const int t = threadIdx.x;

    // build Wh: [q][col] uint2 with k = {2q,2q+1} and {2q+8,2q+9}
    for (int idx = t; idx < 512; idx += 128) {
        int qq = idx >> 7, col = idx & 127;
        float w0, w1, w2, w3;
        if (col < 96) {
            const float* wf = &g_Wfold[(g * 96 + col) * 16];
            w0 = wf[2 * qq];     w1 = wf[2 * qq + 1];
            w2 = wf[2 * qq + 8]; w3 = wf[2 * qq + 9];
        } else {
            const float* wf = &Wcen[(g * 32 + col - 96) * 16];
            w0 = wf[2 * qq];     w1 = wf[2 * qq + 1];
            w2 = wf[2 * qq + 8]; w3 = wf[2 * qq + 9];
        }
        Wh[qq * 132 + col] = make_uint2(pack_h2(w0, w1), pack_h2(w2, w3));
    }
    // (__syncthreads happens inside run_group after gbuf build)

    switch (g >> 1) {
        case 0:  run_group<1, 11>(g, b, x, bhh, out, Wh, gbuf_raw); break;
        case 1:  run_group<11, 1>(g, b, x, bhh, out, Wh, gbuf_raw); break;
        case 2:  run_group<3, 5>(g, b, x, bhh, out, Wh, gbuf_raw); break;
        default: run_group<5, 3>(g, b, x, bhh, out, Wh, gbuf_raw); break;
    }
}

// ============================================================================
extern "C" void kernel_launch(void* const* d_in, const int* in_sizes, int n_in,
                              void* d_out, int out_size) {
    (void)in_sizes; (void)n_in; (void)out_size;
    const float* x    = (const float*)d_in[0];
    const float* Wcen = (const float*)d_in[1];
    const float* W0 = (const float*)d_in[2];  const float* b0 = (const float*)d_in[3];
    const float* W1 = (const float*)d_in[4];  const float* b1 = (const float*)d_in[5];
    const float* W2 = (const float*)d_in[6];  const float* b2 = (const float*)d_in[7];
    const float* W3 = (const float*)d_in[8];  const float* b3 = (const float*)d_in[9];
    const float* Wm  = (const float*)d_in[10];
    const float* Wih = (const float*)d_in[11];
    const float* Whh = (const float*)d_in[12];
    const float* bih = (const float*)d_in[13];
    const float* bhh = (const float*)d_in[14];
    float* out = (float*)d_out;

    pool_kernel<<<1024, 256>>>(x);
    gi_fold_kernel<<<136, 256>>>(W0, b0, W1, b1, W2, b2, W3, b3,
                                 Wm, Wih, bih, Whh, Wcen);
    main_kernel<<<dim3(256, 8), 128>>>(x, Wcen, bhh, out);
}